// round 2
// baseline (speedup 1.0000x reference)
#include <cuda_runtime.h>
#include <cstdint>

#define N_NODES 100000
#define E_EDGES 800000
#define P_PERM  200000
#define L_LEN   16
#define D_DIM   64
#define NUM_BOND 4

// ---------------- scratch (static device allocations are allowed) ------------
__device__ float g_Wf[L_LEN * D_DIM * D_DIM];                    // [a][b][c]  256KB
__device__ float g_BW[L_LEN * NUM_BOND * D_DIM];                 // [a][j][c]   16KB
__device__ float g_NW[(size_t)N_NODES * L_LEN * D_DIM];          // [n][a][c]  410MB

// ============================================================================
// K1: transpose weights -> Wf[a][b][c], and BW[a][j][c] = bond_emb[j] @ W[:,:,a]
// ============================================================================
__global__ void prep_kernel(const float* __restrict__ weights,
                            const float* __restrict__ bond_emb) {
    int idx = blockIdx.x * blockDim.x + threadIdx.x;
    if (idx < L_LEN * D_DIM * D_DIM) {
        int a = idx >> 12;
        int b = (idx >> 6) & 63;
        int c = idx & 63;
        g_Wf[idx] = weights[((b << 6) + c) * L_LEN + a];
    }
    if (idx < L_LEN * NUM_BOND * D_DIM) {
        int a = idx >> 8;
        int j = (idx >> 6) & 3;
        int c = idx & 63;
        float s = 0.f;
        #pragma unroll 8
        for (int b = 0; b < D_DIM; b++)
            s += bond_emb[j * D_DIM + b] * weights[((b << 6) + c) * L_LEN + a];
        g_BW[idx] = s;
    }
}

// ============================================================================
// K2: NW[n][a][c] = sum_b nfeat[n,b] * Wf[a][b][c]
// grid = (ceil(N/128), 16 a-slices), 128 threads, 8x8 microtile per thread.
// ============================================================================
#define XSP 132   // 128 n + pad (keeps 16B alignment: 132 % 4 == 0)
#define WSP 68    // 64 c + pad

__global__ __launch_bounds__(128)
void nw_gemm_kernel(const float* __restrict__ nfeat) {
    extern __shared__ float smem2[];
    float* xs = smem2;              // [64 b][XSP]  (n inner)
    float* ws = smem2 + 64 * XSP;   // [64 b][WSP]  (c inner)

    const int tid = threadIdx.x;
    const int n0  = blockIdx.x * 128;
    const int a   = blockIdx.y;

    // load W slice: 4096 floats
    {
        const float4* wsrc = (const float4*)&g_Wf[a * 4096];
        #pragma unroll
        for (int i = tid; i < 1024; i += 128) {
            float4 v = wsrc[i];
            int b = i >> 4;
            int c = (i & 15) << 2;
            *(float4*)&ws[b * WSP + c] = v;
        }
    }
    // load nfeat tile transposed: xs[b][n]
    #pragma unroll
    for (int i = tid; i < 2048; i += 128) {
        int n  = i >> 4;
        int c4 = (i & 15) << 2;
        float4 v = make_float4(0.f, 0.f, 0.f, 0.f);
        if (n0 + n < N_NODES)
            v = *(const float4*)&nfeat[(size_t)(n0 + n) * D_DIM + c4];
        xs[(c4 + 0) * XSP + n] = v.x;
        xs[(c4 + 1) * XSP + n] = v.y;
        xs[(c4 + 2) * XSP + n] = v.z;
        xs[(c4 + 3) * XSP + n] = v.w;
    }
    __syncthreads();

    const int tn = (tid >> 3) << 3;   // 0..120
    const int tc = (tid & 7) << 3;    // 0..56

    float acc[8][8];
    #pragma unroll
    for (int i = 0; i < 8; i++)
        #pragma unroll
        for (int j = 0; j < 8; j++) acc[i][j] = 0.f;

    #pragma unroll 4
    for (int k = 0; k < 64; k++) {
        float4 x0 = *(const float4*)&xs[k * XSP + tn];
        float4 x1 = *(const float4*)&xs[k * XSP + tn + 4];
        float4 w0 = *(const float4*)&ws[k * WSP + tc];
        float4 w1 = *(const float4*)&ws[k * WSP + tc + 4];
        float xv[8] = {x0.x, x0.y, x0.z, x0.w, x1.x, x1.y, x1.z, x1.w};
        float wv[8] = {w0.x, w0.y, w0.z, w0.w, w1.x, w1.y, w1.z, w1.w};
        #pragma unroll
        for (int i = 0; i < 8; i++)
            #pragma unroll
            for (int j = 0; j < 8; j++)
                acc[i][j] += xv[i] * wv[j];
    }

    #pragma unroll
    for (int i = 0; i < 8; i++) {
        int n = n0 + tn + i;
        if (n < N_NODES) {
            float* dst = &g_NW[((size_t)n << 10) + (a << 6) + tc];
            *(float4*)(dst + 0) = make_float4(acc[i][0], acc[i][1], acc[i][2], acc[i][3]);
            *(float4*)(dst + 4) = make_float4(acc[i][4], acc[i][5], acc[i][6], acc[i][7]);
        }
    }
}

// ============================================================================
// K3: fused gather + einsum-assembly + relu + w_lin + deg-MLP gate + pool scatter
// 256 threads (8 warps), each warp processes 4 batches of 8 permutations.
// ============================================================================
#define FULLM 0xffffffffu

__global__ __launch_bounds__(256)
void fused_kernel(const float* __restrict__ degs,
                  const float* __restrict__ n2p_val,
                  const float* __restrict__ e2p_val,
                  const float* __restrict__ pool_val,
                  const float* __restrict__ bias,
                  const float* __restrict__ w_deg0,
                  const float* __restrict__ b_deg0,
                  const float* __restrict__ w_deg1,
                  const float* __restrict__ b_deg1,
                  const float* __restrict__ w_lin,
                  const float* __restrict__ b_lin,
                  const int*   __restrict__ edge_feat_idx,
                  const int*   __restrict__ n2p_col,
                  const int*   __restrict__ e2p_col,
                  const int*   __restrict__ pool_row,
                  float*       __restrict__ out) {
    extern __shared__ float smem[];
    float* s_BW     = smem;              // 4096  [a][j][c]
    float* s_wlinT  = s_BW + 4096;       // 4096  [k][c]
    float* s_wdeg1T = s_wlinT + 4096;    // 8192  [k][c]
    float* s_wdeg0  = s_wdeg1T + 8192;   // 512   [k][s]
    float* s_bdeg0  = s_wdeg0 + 512;     // 128
    float* s_bias   = s_bdeg0 + 128;     // 64
    float* s_blin   = s_bias + 64;       // 64
    float* s_bdeg1  = s_blin + 64;       // 64
    float* s_h      = s_bdeg1 + 64;      // 8 warps * 8p * 64 = 4096
    float* s_t      = s_h + 4096;        // 8 warps * 8p * 32 = 2048

    const int tid = threadIdx.x;
    // ---- stage constants into shared memory ----
    #pragma unroll
    for (int i = tid; i < 4096; i += 256) s_BW[i] = g_BW[i];
    #pragma unroll
    for (int i = tid; i < 4096; i += 256) {           // transpose w_lin -> [k][c]
        int k = i >> 6, c = i & 63;
        s_wlinT[i] = w_lin[c * 64 + k];
    }
    #pragma unroll
    for (int i = tid; i < 8192; i += 256) {           // transpose w_deg1 -> [k][c]
        int k = i >> 6, c = i & 63;
        s_wdeg1T[i] = w_deg1[c * 128 + k];
    }
    #pragma unroll
    for (int i = tid; i < 512; i += 256) s_wdeg0[i] = w_deg0[i];
    if (tid < 128) s_bdeg0[tid] = b_deg0[tid];
    if (tid < 64) {
        s_bias[tid]  = bias[tid];
        s_blin[tid]  = b_lin[tid];
        s_bdeg1[tid] = b_deg1[tid];
    }
    __syncthreads();

    const int warp = tid >> 5;
    const int lane = tid & 31;
    const int c0   = lane << 1;
    float* sh = s_h + warp * 512;   // [8p][64]
    float* st = s_t + warp * 256;   // [8p][32]

    const int pwarp = (blockIdx.x * 8 + warp) * 32;

    for (int b = 0; b < 4; b++) {
        const int p0 = pwarp + b * 8;
        float ds[8][4];

        // ---------- phase 1: gather NW rows + BW lookup, build relu(h) ----------
        for (int pp = 0; pp < 8; pp++) {
            int p = p0 + pp;
            bool valid = p < P_PERM;
            size_t ib = (size_t)(valid ? p : 0) * 16;
            int nc = 0, ec = 0;
            float vn = 0.f, ve = 0.f;
            if (lane < 16) {
                nc = n2p_col[ib + lane];
                vn = valid ? n2p_val[ib + lane] : 0.f;
                ec = e2p_col[ib + lane];
                ve = valid ? e2p_val[ib + lane] : 0.f;
            }
            int bj = (lane < 16) ? edge_feat_idx[ec] : 0;
            float dsv = 0.f;
            if (lane < 16 && (lane % 5) == 0) dsv = vn * degs[nc];
            ds[pp][0] = __shfl_sync(FULLM, dsv, 0);
            ds[pp][1] = __shfl_sync(FULLM, dsv, 5);
            ds[pp][2] = __shfl_sync(FULLM, dsv, 10);
            ds[pp][3] = __shfl_sync(FULLM, dsv, 15);

            float a0 = s_bias[c0], a1 = s_bias[c0 + 1];
            #pragma unroll
            for (int a = 0; a < 16; a++) {
                int   nca = __shfl_sync(FULLM, nc, a);
                float vna = __shfl_sync(FULLM, vn, a);
                int   bja = __shfl_sync(FULLM, bj, a);
                float vea = __shfl_sync(FULLM, ve, a);
                float2 nw = *(const float2*)&g_NW[((size_t)nca << 10) + (a << 6) + c0];
                float2 bw = *(const float2*)&s_BW[((a << 2) + bja) * 64 + c0];
                a0 += vna * nw.x + vea * bw.x;
                a1 += vna * nw.y + vea * bw.y;
            }
            sh[pp * 64 + c0]     = fmaxf(a0, 0.f);
            sh[pp * 64 + c0 + 1] = fmaxf(a1, 0.f);
        }
        __syncwarp();

        // ---------- phase 2: h2 = relu(h) @ w_lin^T + b_lin (batched over 8 p) ----------
        float h2a0[8], h2a1[8];
        #pragma unroll
        for (int pp = 0; pp < 8; pp++) { h2a0[pp] = s_blin[c0]; h2a1[pp] = s_blin[c0 + 1]; }
        #pragma unroll
        for (int k = 0; k < 64; k += 4) {
            float2 v0 = *(const float2*)&s_wlinT[(k + 0) * 64 + c0];
            float2 v1 = *(const float2*)&s_wlinT[(k + 1) * 64 + c0];
            float2 v2 = *(const float2*)&s_wlinT[(k + 2) * 64 + c0];
            float2 v3 = *(const float2*)&s_wlinT[(k + 3) * 64 + c0];
            #pragma unroll
            for (int pp = 0; pp < 8; pp++) {
                float4 hv = *(const float4*)&sh[pp * 64 + k];
                h2a0[pp] += hv.x * v0.x + hv.y * v1.x + hv.z * v2.x + hv.w * v3.x;
                h2a1[pp] += hv.x * v0.y + hv.y * v1.y + hv.z * v2.y + hv.w * v3.y;
            }
        }

        // ---------- phase 3: gate g = relu(ds @ w_deg0^T + b_deg0) @ w_deg1^T + b_deg1 ----------
        float g0[8], g1[8];
        #pragma unroll
        for (int pp = 0; pp < 8; pp++) { g0[pp] = s_bdeg1[c0]; g1[pp] = s_bdeg1[c0 + 1]; }
        for (int q = 0; q < 4; q++) {
            int k = q * 32 + lane;
            float4 w0 = *(const float4*)&s_wdeg0[k * 4];
            float b0 = s_bdeg0[k];
            #pragma unroll
            for (int pp = 0; pp < 8; pp++) {
                float t = ds[pp][0] * w0.x + ds[pp][1] * w0.y +
                          ds[pp][2] * w0.z + ds[pp][3] * w0.w + b0;
                st[pp * 32 + lane] = fmaxf(t, 0.f);
            }
            __syncwarp();
            #pragma unroll
            for (int kk = 0; kk < 32; kk += 4) {
                int kg = q * 32 + kk;
                float2 u0 = *(const float2*)&s_wdeg1T[(kg + 0) * 64 + c0];
                float2 u1 = *(const float2*)&s_wdeg1T[(kg + 1) * 64 + c0];
                float2 u2 = *(const float2*)&s_wdeg1T[(kg + 2) * 64 + c0];
                float2 u3 = *(const float2*)&s_wdeg1T[(kg + 3) * 64 + c0];
                #pragma unroll
                for (int pp = 0; pp < 8; pp++) {
                    float4 tv = *(const float4*)&st[pp * 32 + kk];
                    g0[pp] += tv.x * u0.x + tv.y * u1.x + tv.z * u2.x + tv.w * u3.x;
                    g1[pp] += tv.x * u0.y + tv.y * u1.y + tv.z * u2.y + tv.w * u3.y;
                }
            }
            __syncwarp();
        }

        // ---------- phase 4: scale by gate and pool_val, scatter-add ----------
        for (int pp = 0; pp < 8; pp++) {
            int p = p0 + pp;
            if (p < P_PERM) {
                float pv = pool_val[p];
                int   pr = pool_row[p];
                atomicAdd(&out[(size_t)pr * 64 + c0],     pv * h2a0[pp] * g0[pp]);
                atomicAdd(&out[(size_t)pr * 64 + c0 + 1], pv * h2a1[pp] * g1[pp]);
            }
        }
    }
}

// ============================================================================
extern "C" void kernel_launch(void* const* d_in, const int* in_sizes, int n_in,
                              void* d_out, int out_size) {
    const float* nfeat         = (const float*)d_in[0];
    const float* degs          = (const float*)d_in[1];
    const float* n2p_val       = (const float*)d_in[2];
    const float* e2p_val       = (const float*)d_in[3];
    const float* pool_val      = (const float*)d_in[4];
    const float* weights       = (const float*)d_in[5];
    const float* bias          = (const float*)d_in[6];
    const float* w_deg0        = (const float*)d_in[7];
    const float* b_deg0        = (const float*)d_in[8];
    const float* w_deg1        = (const float*)d_in[9];
    const float* b_deg1        = (const float*)d_in[10];
    const float* w_lin         = (const float*)d_in[11];
    const float* b_lin         = (const float*)d_in[12];
    const float* bond_emb      = (const float*)d_in[13];
    const int*   edge_feat_idx = (const int*)d_in[14];
    const int*   n2p_col       = (const int*)d_in[16];
    const int*   e2p_col       = (const int*)d_in[18];
    const int*   pool_row      = (const int*)d_in[19];
    float* out = (float*)d_out;

    // out has rows never touched by pool -> must be zero
    cudaMemsetAsync(d_out, 0, (size_t)out_size * sizeof(float), 0);

    // K1: weight transpose + bond @ W precompute
    prep_kernel<<<256, 256>>>(weights, bond_emb);

    // K2: NW = nfeat @ W  (per a-slice)
    const int k2_smem = (64 * XSP + 64 * WSP) * (int)sizeof(float);  // 51200 B
    cudaFuncSetAttribute(nw_gemm_kernel, cudaFuncAttributeMaxDynamicSharedMemorySize, k2_smem);
    dim3 g2((N_NODES + 127) / 128, L_LEN);
    nw_gemm_kernel<<<g2, 128, k2_smem>>>(nfeat);

    // K3: fused gather + epilogues + scatter
    const int k3_smem = 23360 * (int)sizeof(float);                  // 93440 B
    cudaFuncSetAttribute(fused_kernel, cudaFuncAttributeMaxDynamicSharedMemorySize, k3_smem);
    int g3 = (P_PERM + 255) / 256;  // 8 warps * 32 p per CTA
    fused_kernel<<<g3, 256, k3_smem>>>(degs, n2p_val, e2p_val, pool_val, bias,
                                       w_deg0, b_deg0, w_deg1, b_deg1,
                                       w_lin, b_lin,
                                       edge_feat_idx, n2p_col, e2p_col, pool_row,
                                       out);
}

// round 4
// speedup vs baseline: 1.3395x; 1.3395x over previous
#include <cuda_runtime.h>
#include <cuda_bf16.h>
#include <cstdint>

#define P_PERM  200000
#define PT      128
#define NTILES  ((P_PERM + PT - 1) / PT)

#define SWZ(o) ((o) ^ (((o) >> 3) & 0x70))

// pre-swizzled bf16 hi/lo B-operand tables (B stored [n-row][k-col], 128B rows)
__device__ __align__(16) __nv_bfloat16 g_W1h[16 * 64 * 64];  // einsum W: [a][c][b]
__device__ __align__(16) __nv_bfloat16 g_W1l[16 * 64 * 64];
__device__ __align__(16) __nv_bfloat16 g_W2h[64 * 64];       // w_lin: [c][k]
__device__ __align__(16) __nv_bfloat16 g_W2l[64 * 64];
__device__ __align__(16) __nv_bfloat16 g_W3h[2 * 64 * 64];   // w_deg1: [chunk][c][k]
__device__ __align__(16) __nv_bfloat16 g_W3l[2 * 64 * 64];

// ---------------------------- SMEM layout (bytes) ---------------------------
#define XH0 0
#define XL0 16384
#define XH1 32768
#define XL1 49152
#define WH0 65536
#define WL0 73728
#define WH1 81920
#define WL1 90112
#define SBOND 98304    // 256 f
#define SDS   99328    // 512 f
#define SWD0 101376    // 512 f
#define SBD0 103424    // 128 f
#define SBIA 103936    // 64 f
#define SBLI 104192    // 64 f
#define SBD1 104448    // 64 f
#define SPV  104704    // 128 f
#define SPR  105216    // 128 i
#define SMEM_BYTES 105728

// ------------------------------ asm helpers --------------------------------
__device__ __forceinline__ void ldm_x4(uint32_t* r, uint32_t a) {
    asm volatile("ldmatrix.sync.aligned.m8n8.x4.shared.b16 {%0,%1,%2,%3}, [%4];"
                 : "=r"(r[0]), "=r"(r[1]), "=r"(r[2]), "=r"(r[3]) : "r"(a));
}
__device__ __forceinline__ void ldm_x2(uint32_t* r, uint32_t a) {
    asm volatile("ldmatrix.sync.aligned.m8n8.x2.shared.b16 {%0,%1}, [%2];"
                 : "=r"(r[0]), "=r"(r[1]) : "r"(a));
}
__device__ __forceinline__ void mma16816(float* d, const uint32_t* a, const uint32_t* b) {
    asm volatile(
        "mma.sync.aligned.m16n8k16.row.col.f32.bf16.bf16.f32 "
        "{%0,%1,%2,%3}, {%4,%5,%6,%7}, {%8,%9}, {%0,%1,%2,%3};"
        : "+f"(d[0]), "+f"(d[1]), "+f"(d[2]), "+f"(d[3])
        : "r"(a[0]), "r"(a[1]), "r"(a[2]), "r"(a[3]), "r"(b[0]), "r"(b[1]));
}
__device__ __forceinline__ uint32_t s2u(const void* p) {
    uint32_t a;
    asm("{ .reg .u64 t; cvta.to.shared.u64 t, %1; cvt.u32.u64 %0, t; }" : "=r"(a) : "l"(p));
    return a;
}

__device__ __forceinline__ void split_store8(const float* f, char* hd, char* ld) {
    uint16_t uh[8], ul[8];
    #pragma unroll
    for (int j = 0; j < 8; j++) {
        __nv_bfloat16 h = __float2bfloat16(f[j]);
        float r = f[j] - __bfloat162float(h);
        uh[j] = __bfloat16_as_ushort(h);
        ul[j] = __bfloat16_as_ushort(__float2bfloat16(r));
    }
    uint4 hv, lv;
    hv.x = uh[0] | ((uint32_t)uh[1] << 16); hv.y = uh[2] | ((uint32_t)uh[3] << 16);
    hv.z = uh[4] | ((uint32_t)uh[5] << 16); hv.w = uh[6] | ((uint32_t)uh[7] << 16);
    lv.x = ul[0] | ((uint32_t)ul[1] << 16); lv.y = ul[2] | ((uint32_t)ul[3] << 16);
    lv.z = ul[4] | ((uint32_t)ul[5] << 16); lv.w = ul[6] | ((uint32_t)ul[7] << 16);
    *(uint4*)hd = hv; *(uint4*)ld = lv;
}

// ---- m32n64 warp GEMM over K=64 slice: acc += Xhi*Whi + Xhi*Wlo + Xlo*Whi ----
__device__ __forceinline__ void gemm_slice(float acc[2][8][4], uint32_t xh, uint32_t wh,
                                           int rbase, int lane) {
    const uint32_t xl = xh + 16384, wl = wh + 8192;
    const int sub = lane >> 3, rin = lane & 7;
    const uint32_t aRow = (uint32_t)(rbase + ((sub & 1) << 3) + rin) * 128;
    const uint32_t aCol = (uint32_t)((sub >> 1) << 4);
    const uint32_t bRow = (uint32_t)((lane & 7) * 128);
    const uint32_t bCol = (uint32_t)(((lane >> 3) & 1) << 4);
    #pragma unroll
    for (int kc = 0; kc < 4; kc++) {
        uint32_t ah0[4], ah1[4], al0[4], al1[4];
        uint32_t aoff = SWZ(aRow + aCol + kc * 32);
        ldm_x4(ah0, xh + aoff);
        ldm_x4(ah1, xh + aoff + 2048);   // +16 rows
        ldm_x4(al0, xl + aoff);
        ldm_x4(al1, xl + aoff + 2048);
        uint32_t boff = SWZ(bRow + bCol + kc * 32);
        #pragma unroll
        for (int nf = 0; nf < 8; nf++) {
            uint32_t bh[2], bl[2];
            ldm_x2(bh, wh + boff + nf * 1024);
            ldm_x2(bl, wl + boff + nf * 1024);
            mma16816(acc[0][nf], ah0, bh);
            mma16816(acc[1][nf], ah1, bh);
            mma16816(acc[0][nf], ah0, bl);
            mma16816(acc[1][nf], ah1, bl);
            mma16816(acc[0][nf], al0, bh);
            mma16816(acc[1][nf], al1, bh);
        }
    }
}

// half-N (4 n-frags) variant for the gate GEMM
__device__ __forceinline__ void gemm_half(float acc[2][4][4], uint32_t xh, uint32_t wh,
                                          int nf0, int rbase, int lane) {
    const uint32_t xl = xh + 16384, wl = wh + 8192;
    const int sub = lane >> 3, rin = lane & 7;
    const uint32_t aRow = (uint32_t)(rbase + ((sub & 1) << 3) + rin) * 128;
    const uint32_t aCol = (uint32_t)((sub >> 1) << 4);
    const uint32_t bRow = (uint32_t)(((lane & 7) + nf0 * 8) * 128);
    const uint32_t bCol = (uint32_t)(((lane >> 3) & 1) << 4);
    #pragma unroll
    for (int kc = 0; kc < 4; kc++) {
        uint32_t ah0[4], ah1[4], al0[4], al1[4];
        uint32_t aoff = SWZ(aRow + aCol + kc * 32);
        ldm_x4(ah0, xh + aoff);
        ldm_x4(ah1, xh + aoff + 2048);
        ldm_x4(al0, xl + aoff);
        ldm_x4(al1, xl + aoff + 2048);
        uint32_t boff = SWZ(bRow + bCol + kc * 32);
        #pragma unroll
        for (int fn = 0; fn < 4; fn++) {
            uint32_t bh[2], bl[2];
            ldm_x2(bh, wh + boff + fn * 1024);
            ldm_x2(bl, wl + boff + fn * 1024);
            mma16816(acc[0][fn], ah0, bh);
            mma16816(acc[1][fn], ah1, bh);
            mma16816(acc[0][fn], ah0, bl);
            mma16816(acc[1][fn], ah1, bl);
            mma16816(acc[0][fn], al0, bh);
            mma16816(acc[1][fn], al1, bh);
        }
    }
}

// ============================================================================
__global__ void prep_kernel(const float* __restrict__ weights,
                            const float* __restrict__ w_lin,
                            const float* __restrict__ w_deg1) {
    int idx = blockIdx.x * blockDim.x + threadIdx.x;  // 65536
    {
        int a = idx >> 12, r = idx & 4095, c = r >> 6, b = r & 63;
        float w = weights[(((b << 6) + c) << 4) + a];
        __nv_bfloat16 h = __float2bfloat16(w);
        __nv_bfloat16 l = __float2bfloat16(w - __bfloat162float(h));
        int off = SWZ(c * 128 + b * 2) >> 1;
        g_W1h[(a << 12) + off] = h;
        g_W1l[(a << 12) + off] = l;
    }
    if (idx < 4096) {
        int c = idx >> 6, k = idx & 63;
        float w = w_lin[(c << 6) + k];
        __nv_bfloat16 h = __float2bfloat16(w);
        __nv_bfloat16 l = __float2bfloat16(w - __bfloat162float(h));
        int off = SWZ(c * 128 + k * 2) >> 1;
        g_W2h[off] = h; g_W2l[off] = l;
    }
    if (idx < 8192) {
        int ch = idx >> 12, r = idx & 4095, c = r >> 6, k = r & 63;
        float w = w_deg1[(c << 7) + (ch << 6) + k];
        __nv_bfloat16 h = __float2bfloat16(w);
        __nv_bfloat16 l = __float2bfloat16(w - __bfloat162float(h));
        int off = SWZ(c * 128 + k * 2) >> 1;
        g_W3h[(ch << 12) + off] = h; g_W3l[(ch << 12) + off] = l;
    }
}

// ============================================================================
__global__ __launch_bounds__(256, 2)
void fused_kernel(const float* __restrict__ nfeat,
                  const float* __restrict__ degs,
                  const float* __restrict__ n2p_val,
                  const float* __restrict__ e2p_val,
                  const float* __restrict__ pool_val,
                  const float* __restrict__ bias,
                  const float* __restrict__ w_deg0,
                  const float* __restrict__ b_deg0,
                  const float* __restrict__ b_deg1,
                  const float* __restrict__ b_lin,
                  const float* __restrict__ bond_emb,
                  const int*   __restrict__ edge_feat_idx,
                  const int*   __restrict__ n2p_col,
                  const int*   __restrict__ e2p_col,
                  const int*   __restrict__ pool_row,
                  float*       __restrict__ out) {
    extern __shared__ char sm[];
    const uint32_t SB = s2u(sm);
    const int tid = threadIdx.x;
    const int warp = tid >> 5, lane = tid & 31;
    const int p0 = blockIdx.x * PT;

    float* s_bond = (float*)(sm + SBOND);
    float* s_ds   = (float*)(sm + SDS);
    float* s_wd0  = (float*)(sm + SWD0);
    float* s_bd0  = (float*)(sm + SBD0);
    float* s_bia  = (float*)(sm + SBIA);
    float* s_bli  = (float*)(sm + SBLI);
    float* s_bd1  = (float*)(sm + SBD1);
    float* s_pv   = (float*)(sm + SPV);
    int*   s_pr   = (int*)(sm + SPR);

    for (int i = tid; i < 256; i += 256) s_bond[i] = bond_emb[i];
    for (int i = tid; i < 512; i += 256) s_wd0[i] = w_deg0[i];
    if (tid < 128) s_bd0[tid] = b_deg0[tid];
    if (tid < 64) { s_bia[tid] = bias[tid]; s_bli[tid] = b_lin[tid]; s_bd1[tid] = b_deg1[tid]; }
    __syncthreads();

    const int rbase = (warp & 3) * 32;
    const uint32_t xbuf[2] = {SB + XH0, SB + XH1};
    const uint32_t wbuf[2] = {SB + WH0, SB + WH1};

    float acc1[2][8][4];
    #pragma unroll
    for (int m = 0; m < 2; m++)
        #pragma unroll
        for (int n = 0; n < 8; n++)
            #pragma unroll
            for (int j = 0; j < 4; j++) acc1[m][n][j] = 0.f;

    const int p = tid - 128;                 // producer row id
    const bool valid = (p0 + p) < P_PERM;    // (only meaningful for warp>=4)
    const int pc = ((p0 + p) < P_PERM) ? (p0 + p) : (P_PERM - 1);

    // ===================== einsum mainloop (16 slices, pipelined) ============
    for (int ag = 0; ag < 4; ag++) {
        int ncs[4], ecs[4];
        float vns[4], ves[4];
        if (warp >= 4) {
            int4 nc4 = ((const int4*)n2p_col)[pc * 4 + ag];
            int4 ec4 = ((const int4*)e2p_col)[pc * 4 + ag];
            float4 vn4 = ((const float4*)n2p_val)[pc * 4 + ag];
            float4 ve4 = ((const float4*)e2p_val)[pc * 4 + ag];
            ncs[0] = nc4.x; ncs[1] = nc4.y; ncs[2] = nc4.z; ncs[3] = nc4.w;
            ecs[0] = ec4.x; ecs[1] = ec4.y; ecs[2] = ec4.z; ecs[3] = ec4.w;
            vns[0] = vn4.x; vns[1] = vn4.y; vns[2] = vn4.z; vns[3] = vn4.w;
            ves[0] = ve4.x; ves[1] = ve4.y; ves[2] = ve4.z; ves[3] = ve4.w;
        }
        #pragma unroll
        for (int ai = 0; ai < 4; ai++) {
            const int b = ai & 1;
            if (warp >= 4) {
                const int a = ag * 4 + ai;
                int nc = ncs[ai], bj = edge_feat_idx[ecs[ai]];
                float vn = valid ? vns[ai] : 0.f;
                float ve = valid ? ves[ai] : 0.f;
                if (ai == ag) s_ds[p * 4 + ag] = vn * degs[nc];
                const float4* nrow = (const float4*)(nfeat + ((size_t)nc << 6));
                const float4* brow = (const float4*)(s_bond + (bj << 6));
                char* xh = sm + (b ? XH1 : XH0);
                #pragma unroll
                for (int g = 0; g < 8; g++) {
                    float4 n0 = nrow[2 * g], n1 = nrow[2 * g + 1];
                    float4 c0 = brow[2 * g], c1 = brow[2 * g + 1];
                    float f[8];
                    f[0] = vn * n0.x + ve * c0.x; f[1] = vn * n0.y + ve * c0.y;
                    f[2] = vn * n0.z + ve * c0.z; f[3] = vn * n0.w + ve * c0.w;
                    f[4] = vn * n1.x + ve * c1.x; f[5] = vn * n1.y + ve * c1.y;
                    f[6] = vn * n1.z + ve * c1.z; f[7] = vn * n1.w + ve * c1.w;
                    uint32_t off = SWZ((uint32_t)p * 128 + g * 16);
                    split_store8(f, xh + off, xh + 16384 + off);
                }
                // copy W1 slice (pre-swizzled)
                const uint4* gwh = (const uint4*)(g_W1h + (a << 12));
                const uint4* gwl = (const uint4*)(g_W1l + (a << 12));
                uint4* dwh = (uint4*)(sm + (b ? WH1 : WH0));
                uint4* dwl = (uint4*)(sm + (b ? WL1 : WL0));
                #pragma unroll
                for (int j = 0; j < 4; j++) {
                    dwh[p + j * 128] = gwh[p + j * 128];
                    dwl[p + j * 128] = gwl[p + j * 128];
                }
            } else if (ag + ai > 0) {
                gemm_slice(acc1, xbuf[b ^ 1], wbuf[b ^ 1], rbase, lane);
            }
            __syncthreads();
        }
    }

    // ===================== epilogue phase A ==================================
    if (warp < 4) {
        gemm_slice(acc1, xbuf[1], wbuf[1], rbase, lane);   // slice 15
        // relu(acc1 + bias) -> hi/lo into buf1
        #pragma unroll
        for (int mt = 0; mt < 2; mt++)
            #pragma unroll
            for (int nf = 0; nf < 8; nf++) {
                int c0 = nf * 8 + (lane & 3) * 2;
                #pragma unroll
                for (int pr2 = 0; pr2 < 2; pr2++) {
                    int row = rbase + mt * 16 + (lane >> 2) + pr2 * 8;
                    float f0 = fmaxf(acc1[mt][nf][pr2 * 2 + 0] + s_bia[c0], 0.f);
                    float f1 = fmaxf(acc1[mt][nf][pr2 * 2 + 1] + s_bia[c0 + 1], 0.f);
                    __nv_bfloat16 h0 = __float2bfloat16(f0), h1 = __float2bfloat16(f1);
                    float r0 = f0 - __bfloat162float(h0), r1 = f1 - __bfloat162float(h1);
                    uint32_t hv = (uint32_t)__bfloat16_as_ushort(h0) |
                                  ((uint32_t)__bfloat16_as_ushort(h1) << 16);
                    uint32_t lv = (uint32_t)__bfloat16_as_ushort(__float2bfloat16(r0)) |
                                  ((uint32_t)__bfloat16_as_ushort(__float2bfloat16(r1)) << 16);
                    uint32_t off = SWZ((uint32_t)row * 128 + c0 * 2);
                    *(uint32_t*)(sm + XH1 + off) = hv;
                    *(uint32_t*)(sm + XL1 + off) = lv;
                }
            }
    } else {
        // W2 -> wbuf0 ; t chunk0 -> buf0 ; pool -> smem
        #pragma unroll
        for (int j = 0; j < 4; j++) {
            ((uint4*)(sm + WH0))[p + j * 128] = ((const uint4*)g_W2h)[p + j * 128];
            ((uint4*)(sm + WL0))[p + j * 128] = ((const uint4*)g_W2l)[p + j * 128];
        }
        float4 dv = *(const float4*)&s_ds[p * 4];
        #pragma unroll
        for (int g = 0; g < 8; g++) {
            float f[8];
            #pragma unroll
            for (int j = 0; j < 8; j++) {
                int k = g * 8 + j;
                float4 w = *(const float4*)&s_wd0[k * 4];
                f[j] = fmaxf(dv.x * w.x + dv.y * w.y + dv.z * w.z + dv.w * w.w + s_bd0[k], 0.f);
            }
            uint32_t off = SWZ((uint32_t)p * 128 + g * 16);
            split_store8(f, sm + XH0 + off, sm + XL0 + off);
        }
        s_pv[p] = valid ? pool_val[p0 + p] : 0.f;
        s_pr[p] = valid ? pool_row[p0 + p] : 0;
    }
    __syncthreads();

    // ===================== epilogue phase B: acc2 = h @ W2^T =================
    float acc2[2][8][4];
    if (warp < 4) {
        #pragma unroll
        for (int m = 0; m < 2; m++)
            #pragma unroll
            for (int n = 0; n < 8; n++)
                #pragma unroll
                for (int j = 0; j < 4; j++) acc2[m][n][j] = 0.f;
        gemm_slice(acc2, xbuf[1], wbuf[0], rbase, lane);
    } else {
        // W3 chunk0 -> wbuf1
        #pragma unroll
        for (int j = 0; j < 4; j++) {
            ((uint4*)(sm + WH1))[p + j * 128] = ((const uint4*)g_W3h)[p + j * 128];
            ((uint4*)(sm + WL1))[p + j * 128] = ((const uint4*)g_W3l)[p + j * 128];
        }
    }
    __syncthreads();

    // ===================== epilogue phase C: t chunk1 + W3 chunk1 ============
    if (warp >= 4) {
        float4 dv = *(const float4*)&s_ds[p * 4];
        #pragma unroll
        for (int g = 0; g < 8; g++) {
            float f[8];
            #pragma unroll
            for (int j = 0; j < 8; j++) {
                int k = 64 + g * 8 + j;
                float4 w = *(const float4*)&s_wd0[k * 4];
                f[j] = fmaxf(dv.x * w.x + dv.y * w.y + dv.z * w.z + dv.w * w.w + s_bd0[k], 0.f);
            }
            uint32_t off = SWZ((uint32_t)p * 128 + g * 16);
            split_store8(f, sm + XH1 + off, sm + XL1 + off);
        }
        #pragma unroll
        for (int j = 0; j < 4; j++) {
            ((uint4*)(sm + WH0))[p + j * 128] = ((const uint4*)(g_W3h + 4096))[p + j * 128];
            ((uint4*)(sm + WL0))[p + j * 128] = ((const uint4*)(g_W3l + 4096))[p + j * 128];
        }
    }
    __syncthreads();

    // ===================== epilogue phase D: gate + combine + scatter ========
    if (warp < 4) {
        #pragma unroll
        for (int half = 0; half < 2; half++) {
            float acc3[2][4][4];
            #pragma unroll
            for (int m = 0; m < 2; m++)
                #pragma unroll
                for (int n = 0; n < 4; n++)
                    #pragma unroll
                    for (int j = 0; j < 4; j++) acc3[m][n][j] = 0.f;
            gemm_half(acc3, xbuf[0], wbuf[1], half * 4, rbase, lane);  // t0 x W3c0
            gemm_half(acc3, xbuf[1], wbuf[0], half * 4, rbase, lane);  // t1 x W3c1
            #pragma unroll
            for (int mt = 0; mt < 2; mt++)
                #pragma unroll
                for (int fn = 0; fn < 4; fn++) {
                    int nf = half * 4 + fn;
                    int c0 = nf * 8 + (lane & 3) * 2;
                    #pragma unroll
                    for (int pr2 = 0; pr2 < 2; pr2++) {
                        int row = rbase + mt * 16 + (lane >> 2) + pr2 * 8;
                        if (p0 + row < P_PERM) {
                            float pv = s_pv[row];
                            int pr = s_pr[row];
                            float h2a = acc2[mt][nf][pr2 * 2 + 0] + s_bli[c0];
                            float h2b = acc2[mt][nf][pr2 * 2 + 1] + s_bli[c0 + 1];
                            float ga  = acc3[mt][fn][pr2 * 2 + 0] + s_bd1[c0];
                            float gb  = acc3[mt][fn][pr2 * 2 + 1] + s_bd1[c0 + 1];
                            atomicAdd(&out[((size_t)pr << 6) + c0], pv * h2a * ga);
                            atomicAdd(&out[((size_t)pr << 6) + c0 + 1], pv * h2b * gb);
                        }
                    }
                }
        }
    }
}

// ============================================================================
extern "C" void kernel_launch(void* const* d_in, const int* in_sizes, int n_in,
                              void* d_out, int out_size) {
    const float* nfeat         = (const float*)d_in[0];
    const float* degs          = (const float*)d_in[1];
    const float* n2p_val       = (const float*)d_in[2];
    const float* e2p_val       = (const float*)d_in[3];
    const float* pool_val      = (const float*)d_in[4];
    const float* weights       = (const float*)d_in[5];
    const float* bias          = (const float*)d_in[6];
    const float* w_deg0        = (const float*)d_in[7];
    const float* b_deg0        = (const float*)d_in[8];
    const float* w_deg1        = (const float*)d_in[9];
    const float* b_deg1        = (const float*)d_in[10];
    const float* w_lin         = (const float*)d_in[11];
    const float* b_lin         = (const float*)d_in[12];
    const float* bond_emb      = (const float*)d_in[13];
    const int*   edge_feat_idx = (const int*)d_in[14];
    const int*   n2p_col       = (const int*)d_in[16];
    const int*   e2p_col       = (const int*)d_in[18];
    const int*   pool_row      = (const int*)d_in[19];
    float* out = (float*)d_out;

    cudaMemsetAsync(d_out, 0, (size_t)out_size * sizeof(float), 0);
    prep_kernel<<<256, 256>>>(weights, w_lin, w_deg1);

    cudaFuncSetAttribute(fused_kernel, cudaFuncAttributeMaxDynamicSharedMemorySize, SMEM_BYTES);
    fused_kernel<<<NTILES, 256, SMEM_BYTES>>>(nfeat, degs, n2p_val, e2p_val, pool_val,
                                              bias, w_deg0, b_deg0, b_deg1, b_lin,
                                              bond_emb, edge_feat_idx, n2p_col, e2p_col,
                                              pool_row, out);
}

// round 5
// speedup vs baseline: 1.6979x; 1.2675x over previous
#include <cuda_runtime.h>
#include <cuda_bf16.h>
#include <cstdint>

#define P_PERM  200000
#define PT      128
#define NTILES  ((P_PERM + PT - 1) / PT)
#define FULLM   0xffffffffu

#define SWZ(o) ((o) ^ (((o) >> 3) & 0x70))

// B operands pre-packed in mma fragment layout: per (slice, kc, nf): 32 lanes x uint4
// uint4 = {pack(h_k0,h_k1), pack(h_k8,h_k9), pack(l_k0,l_k1), pack(l_k8,l_k9)}
__device__ __align__(16) uint4 g_W1f[16 * 4 * 8 * 32];  // einsum weights, 256KB
__device__ __align__(16) uint4 g_W2f[4 * 8 * 32];       // w_lin, 16KB
__device__ __align__(16) uint4 g_W3f[2 * 4 * 8 * 32];   // w_deg1 (2 k-chunks), 32KB

// ---------------------------- SMEM layout (bytes) ---------------------------
#define XH0 0          // X tile slot0 hi (16KB); lo at +16384
#define XH1 32768      // X tile slot1 hi; lo at +16384
#define TH  65536      // relu(h) hi; lo at +16384
#define SBOND 98304    // 256 f
#define SDS   99328    // 512 f
#define SWD0 101376    // 512 f
#define SBD0 103424    // 128 f
#define SBIA 103936    // 64 f
#define SBLI 104192    // 64 f
#define SBD1 104448    // 64 f
#define SPV  104704    // 128 f
#define SPR  105216    // 128 i
#define SMEM_BYTES 105728

// ------------------------------ asm helpers --------------------------------
__device__ __forceinline__ void ldm_x4(uint32_t* r, uint32_t a) {
    asm volatile("ldmatrix.sync.aligned.m8n8.x4.shared.b16 {%0,%1,%2,%3}, [%4];"
                 : "=r"(r[0]), "=r"(r[1]), "=r"(r[2]), "=r"(r[3]) : "r"(a));
}
__device__ __forceinline__ void mma16816(float* d, const uint32_t* a, const uint32_t* b) {
    asm volatile(
        "mma.sync.aligned.m16n8k16.row.col.f32.bf16.bf16.f32 "
        "{%0,%1,%2,%3}, {%4,%5,%6,%7}, {%8,%9}, {%0,%1,%2,%3};"
        : "+f"(d[0]), "+f"(d[1]), "+f"(d[2]), "+f"(d[3])
        : "r"(a[0]), "r"(a[1]), "r"(a[2]), "r"(a[3]), "r"(b[0]), "r"(b[1]));
}
__device__ __forceinline__ uint32_t s2u(const void* p) {
    uint32_t a;
    asm("{ .reg .u64 t; cvta.to.shared.u64 t, %1; cvt.u32.u64 %0, t; }" : "=r"(a) : "l"(p));
    return a;
}

__device__ __forceinline__ uint32_t pack_bf2(float a, float b) {
    return (uint32_t)__bfloat16_as_ushort(__float2bfloat16(a)) |
           ((uint32_t)__bfloat16_as_ushort(__float2bfloat16(b)) << 16);
}

__device__ __forceinline__ void split_store8(const float* f, char* hd, char* ld) {
    float h[8], l[8];
    #pragma unroll
    for (int j = 0; j < 8; j++) {
        __nv_bfloat16 hb = __float2bfloat16(f[j]);
        h[j] = __bfloat162float(hb);
        l[j] = f[j] - h[j];
    }
    uint4 hv, lv;
    hv.x = pack_bf2(h[0], h[1]); hv.y = pack_bf2(h[2], h[3]);
    hv.z = pack_bf2(h[4], h[5]); hv.w = pack_bf2(h[6], h[7]);
    lv.x = pack_bf2(l[0], l[1]); lv.y = pack_bf2(l[2], l[3]);
    lv.z = pack_bf2(l[4], l[5]); lv.w = pack_bf2(l[6], l[7]);
    *(uint4*)hd = hv; *(uint4*)ld = lv;
}

// ---- m32 x n(8*NF) warp GEMM over K=64: acc += Xh*Wh + Xh*Wl + Xl*Wh --------
// A: swizzled smem tile (hi at xh, lo at xh+16384); B: gmem fragments.
template<int NF>
__device__ __forceinline__ void gemm_tile(float (&acc)[2][NF][4], uint32_t xh,
                                          const uint4* __restrict__ wf, int nf0,
                                          int rbase, int lane) {
    const uint32_t xl = xh + 16384;
    const int sub = lane >> 3, rin = lane & 7;
    const uint32_t aRow = (uint32_t)(rbase + ((sub & 1) << 3) + rin) * 128;
    const uint32_t aCol = (uint32_t)((sub >> 1) << 4);
    #pragma unroll
    for (int kc = 0; kc < 4; kc++) {
        uint32_t aoff = SWZ(aRow + aCol + kc * 32);
        uint32_t ah0[4], ah1[4], al0[4], al1[4];
        ldm_x4(ah0, xh + aoff);
        ldm_x4(ah1, xh + aoff + 2048);   // +16 rows
        ldm_x4(al0, xl + aoff);
        ldm_x4(al1, xl + aoff + 2048);
        #pragma unroll
        for (int nfg = 0; nfg < NF; nfg += 4) {
            uint4 bfr[4];
            #pragma unroll
            for (int q = 0; q < 4; q++)
                bfr[q] = wf[(kc * 8 + nf0 + nfg + q) * 32 + lane];
            #pragma unroll
            for (int q = 0; q < 4; q++) {
                const int nf = nfg + q;
                uint32_t bh[2] = {bfr[q].x, bfr[q].y};
                uint32_t bl[2] = {bfr[q].z, bfr[q].w};
                mma16816(acc[0][nf], ah0, bh);
                mma16816(acc[1][nf], ah1, bh);
                mma16816(acc[0][nf], ah0, bl);
                mma16816(acc[1][nf], ah1, bl);
                mma16816(acc[0][nf], al0, bh);
                mma16816(acc[1][nf], al1, bh);
            }
        }
    }
}

// ============================================================================
// prep: build B-fragment tables (hi/lo bf16 split)
// ============================================================================
__device__ __forceinline__ uint4 make_frag(float w0, float w1, float w8, float w9) {
    __nv_bfloat16 h0 = __float2bfloat16(w0), h1 = __float2bfloat16(w1);
    __nv_bfloat16 h8 = __float2bfloat16(w8), h9 = __float2bfloat16(w9);
    uint4 v;
    v.x = (uint32_t)__bfloat16_as_ushort(h0) | ((uint32_t)__bfloat16_as_ushort(h1) << 16);
    v.y = (uint32_t)__bfloat16_as_ushort(h8) | ((uint32_t)__bfloat16_as_ushort(h9) << 16);
    v.z = pack_bf2(w0 - __bfloat162float(h0), w1 - __bfloat162float(h1));
    v.w = pack_bf2(w8 - __bfloat162float(h8), w9 - __bfloat162float(h9));
    return v;
}

__global__ void prep_kernel(const float* __restrict__ weights,
                            const float* __restrict__ w_lin,
                            const float* __restrict__ w_deg1) {
    int idx = blockIdx.x * 256 + threadIdx.x;    // 0..16383
    const int lane = idx & 31;
    const int nf = (idx >> 5) & 7;
    const int kc = (idx >> 8) & 3;
    const int c = nf * 8 + (lane >> 2);
    const int kb = kc * 16 + (lane & 3) * 2;
    {
        int a = idx >> 10;
        float w0 = weights[(((kb + 0) << 6) + c) * 16 + a];
        float w1 = weights[(((kb + 1) << 6) + c) * 16 + a];
        float w8 = weights[(((kb + 8) << 6) + c) * 16 + a];
        float w9 = weights[(((kb + 9) << 6) + c) * 16 + a];
        g_W1f[idx] = make_frag(w0, w1, w8, w9);
    }
    if (idx < 1024) {
        const float* s = w_lin + c * 64;
        g_W2f[idx] = make_frag(s[kb], s[kb + 1], s[kb + 8], s[kb + 9]);
    }
    if (idx < 2048) {
        int ch = idx >> 10;
        const float* s = w_deg1 + c * 128 + ch * 64;
        g_W3f[idx] = make_frag(s[kb], s[kb + 1], s[kb + 8], s[kb + 9]);
    }
}

// ============================================================================
__global__ __launch_bounds__(256, 2)
void fused_kernel(const float* __restrict__ nfeat,
                  const float* __restrict__ degs,
                  const float* __restrict__ n2p_val,
                  const float* __restrict__ e2p_val,
                  const float* __restrict__ pool_val,
                  const float* __restrict__ bias,
                  const float* __restrict__ w_deg0,
                  const float* __restrict__ b_deg0,
                  const float* __restrict__ b_deg1,
                  const float* __restrict__ b_lin,
                  const float* __restrict__ bond_emb,
                  const int*   __restrict__ edge_feat_idx,
                  const int*   __restrict__ n2p_col,
                  const int*   __restrict__ e2p_col,
                  const int*   __restrict__ pool_row,
                  float*       __restrict__ out) {
    extern __shared__ char sm[];
    const uint32_t SB = s2u(sm);
    const int tid = threadIdx.x;
    const int warp = tid >> 5, lane = tid & 31;
    const int p0 = blockIdx.x * PT;

    float* s_bond = (float*)(sm + SBOND);
    float* s_ds   = (float*)(sm + SDS);
    float* s_wd0  = (float*)(sm + SWD0);
    float* s_bd0  = (float*)(sm + SBD0);
    float* s_bia  = (float*)(sm + SBIA);
    float* s_bli  = (float*)(sm + SBLI);
    float* s_bd1  = (float*)(sm + SBD1);
    float* s_pv   = (float*)(sm + SPV);
    int*   s_pr   = (int*)(sm + SPR);

    for (int i = tid; i < 256; i += 256) s_bond[i] = bond_emb[i];
    for (int i = tid; i < 512; i += 256) s_wd0[i] = w_deg0[i];
    if (tid < 128) s_bd0[tid] = b_deg0[tid];
    if (tid < 64) { s_bia[tid] = bias[tid]; s_bli[tid] = b_lin[tid]; s_bd1[tid] = b_deg1[tid]; }
    __syncthreads();

    const int rbase = (warp & 3) * 32;
    const uint32_t xbuf[2] = {SB + XH0, SB + XH1};

    float acc1[2][8][4];
    #pragma unroll
    for (int m = 0; m < 2; m++)
        #pragma unroll
        for (int n = 0; n < 8; n++)
            #pragma unroll
            for (int j = 0; j < 4; j++) acc1[m][n][j] = 0.f;

    const int p = tid - 128;                 // producer row id (warp>=4)
    const bool valid = (p0 + p) < P_PERM;
    const int pc = valid ? (p0 + p) : (P_PERM - 1);

    // ===================== einsum mainloop (16 slices, double-buffered) ======
    for (int ag = 0; ag < 4; ag++) {
        int ncs[4], ecs[4];
        float vns[4], ves[4];
        if (warp >= 4) {
            int4 nc4 = ((const int4*)n2p_col)[pc * 4 + ag];
            int4 ec4 = ((const int4*)e2p_col)[pc * 4 + ag];
            float4 vn4 = ((const float4*)n2p_val)[pc * 4 + ag];
            float4 ve4 = ((const float4*)e2p_val)[pc * 4 + ag];
            ncs[0] = nc4.x; ncs[1] = nc4.y; ncs[2] = nc4.z; ncs[3] = nc4.w;
            ecs[0] = ec4.x; ecs[1] = ec4.y; ecs[2] = ec4.z; ecs[3] = ec4.w;
            vns[0] = vn4.x; vns[1] = vn4.y; vns[2] = vn4.z; vns[3] = vn4.w;
            ves[0] = ve4.x; ves[1] = ve4.y; ves[2] = ve4.z; ves[3] = ve4.w;
        }
        #pragma unroll
        for (int ai = 0; ai < 4; ai++) {
            const int a = ag * 4 + ai;
            const int b = a & 1;
            if (warp >= 4) {
                int nc = ncs[ai];
                int bj = edge_feat_idx[ecs[ai]];
                float vn = valid ? vns[ai] : 0.f;
                float ve = valid ? ves[ai] : 0.f;
                if (ai == ag) s_ds[p * 4 + ag] = vn * degs[nc];
                char* xh = sm + (b ? XH1 : XH0);
                char* xl = xh + 16384;
                const int r0 = (warp - 4) * 32;
                #pragma unroll
                for (int pass = 0; pass < 8; pass++) {
                    int src = pass * 4 + (lane >> 3);
                    int   nc_r = __shfl_sync(FULLM, nc, src);
                    int   bj_r = __shfl_sync(FULLM, bj, src);
                    float vn_r = __shfl_sync(FULLM, vn, src);
                    float ve_r = __shfl_sync(FULLM, ve, src);
                    int row = r0 + pass * 4 + (lane >> 3);
                    const float4* nrow = (const float4*)(nfeat + ((size_t)nc_r << 6)) + ((lane & 7) << 1);
                    const float4* brow = (const float4*)(s_bond + (bj_r << 6)) + ((lane & 7) << 1);
                    float4 n0 = nrow[0], n1 = nrow[1];
                    float4 c0 = brow[0], c1 = brow[1];
                    float f[8];
                    f[0] = vn_r * n0.x + ve_r * c0.x; f[1] = vn_r * n0.y + ve_r * c0.y;
                    f[2] = vn_r * n0.z + ve_r * c0.z; f[3] = vn_r * n0.w + ve_r * c0.w;
                    f[4] = vn_r * n1.x + ve_r * c1.x; f[5] = vn_r * n1.y + ve_r * c1.y;
                    f[6] = vn_r * n1.z + ve_r * c1.z; f[7] = vn_r * n1.w + ve_r * c1.w;
                    uint32_t off = SWZ((uint32_t)row * 128 + ((lane & 7) << 4));
                    split_store8(f, xh + off, xl + off);
                }
            } else if (a > 0) {
                gemm_tile<8>(acc1, xbuf[b ^ 1], g_W1f + (a - 1) * 1024, 0, rbase, lane);
            }
            __syncthreads();
        }
    }

    // ===================== epilogue phase A ==================================
    // consumers: gemm slice15 (X1), relu(acc1+bias) -> TH/TL
    // producers: t0 (k 0..63) -> X0, pool staging
    if (warp < 4) {
        gemm_tile<8>(acc1, xbuf[1], g_W1f + 15 * 1024, 0, rbase, lane);
        #pragma unroll
        for (int mt = 0; mt < 2; mt++)
            #pragma unroll
            for (int nf = 0; nf < 8; nf++) {
                int c0 = nf * 8 + (lane & 3) * 2;
                #pragma unroll
                for (int pr2 = 0; pr2 < 2; pr2++) {
                    int row = rbase + mt * 16 + (lane >> 2) + pr2 * 8;
                    float f0 = fmaxf(acc1[mt][nf][pr2 * 2 + 0] + s_bia[c0], 0.f);
                    float f1 = fmaxf(acc1[mt][nf][pr2 * 2 + 1] + s_bia[c0 + 1], 0.f);
                    __nv_bfloat16 h0 = __float2bfloat16(f0), h1 = __float2bfloat16(f1);
                    uint32_t hv = (uint32_t)__bfloat16_as_ushort(h0) |
                                  ((uint32_t)__bfloat16_as_ushort(h1) << 16);
                    uint32_t lv = pack_bf2(f0 - __bfloat162float(h0), f1 - __bfloat162float(h1));
                    uint32_t off = SWZ((uint32_t)row * 128 + (uint32_t)c0 * 2);
                    *(uint32_t*)(sm + TH + off) = hv;
                    *(uint32_t*)(sm + TH + 16384 + off) = lv;
                }
            }
    } else {
        float4 dv = *(const float4*)&s_ds[p * 4];
        #pragma unroll
        for (int g = 0; g < 8; g++) {
            float f[8];
            #pragma unroll
            for (int j = 0; j < 8; j++) {
                int k = g * 8 + j;
                float4 w = *(const float4*)&s_wd0[k * 4];
                f[j] = fmaxf(dv.x * w.x + dv.y * w.y + dv.z * w.z + dv.w * w.w + s_bd0[k], 0.f);
            }
            uint32_t off = SWZ((uint32_t)p * 128 + g * 16);
            split_store8(f, sm + XH0 + off, sm + XH0 + 16384 + off);
        }
        s_pv[p] = valid ? pool_val[p0 + p] : 0.f;
        s_pr[p] = valid ? pool_row[p0 + p] : 0;
    }
    __syncthreads();

    // ===================== epilogue phase B ==================================
    // consumers: acc2 = relu(h) @ W2^T (reads TH); producers: t1 (k 64..127) -> X1
    float acc2[2][8][4];
    if (warp < 4) {
        #pragma unroll
        for (int m = 0; m < 2; m++)
            #pragma unroll
            for (int n = 0; n < 8; n++)
                #pragma unroll
                for (int j = 0; j < 4; j++) acc2[m][n][j] = 0.f;
        gemm_tile<8>(acc2, SB + TH, g_W2f, 0, rbase, lane);
    } else {
        float4 dv = *(const float4*)&s_ds[p * 4];
        #pragma unroll
        for (int g = 0; g < 8; g++) {
            float f[8];
            #pragma unroll
            for (int j = 0; j < 8; j++) {
                int k = 64 + g * 8 + j;
                float4 w = *(const float4*)&s_wd0[k * 4];
                f[j] = fmaxf(dv.x * w.x + dv.y * w.y + dv.z * w.z + dv.w * w.w + s_bd0[k], 0.f);
            }
            uint32_t off = SWZ((uint32_t)p * 128 + g * 16);
            split_store8(f, sm + XH1 + off, sm + XH1 + 16384 + off);
        }
    }
    __syncthreads();

    // ===================== epilogue phase C: gate, combine, scatter ==========
    if (warp < 4) {
        #pragma unroll
        for (int half = 0; half < 2; half++) {
            float acc3[2][4][4];
            #pragma unroll
            for (int m = 0; m < 2; m++)
                #pragma unroll
                for (int n = 0; n < 4; n++)
                    #pragma unroll
                    for (int j = 0; j < 4; j++) acc3[m][n][j] = 0.f;
            gemm_tile<4>(acc3, SB + XH0, g_W3f, half * 4, rbase, lane);         // t0 x W3 chunk0
            gemm_tile<4>(acc3, SB + XH1, g_W3f + 1024, half * 4, rbase, lane);  // t1 x W3 chunk1
            #pragma unroll
            for (int mt = 0; mt < 2; mt++)
                #pragma unroll
                for (int fn = 0; fn < 4; fn++) {
                    int nf = half * 4 + fn;
                    int c0 = nf * 8 + (lane & 3) * 2;
                    #pragma unroll
                    for (int pr2 = 0; pr2 < 2; pr2++) {
                        int row = rbase + mt * 16 + (lane >> 2) + pr2 * 8;
                        if (p0 + row < P_PERM) {
                            float pv = s_pv[row];
                            int pr = s_pr[row];
                            float h2a = acc2[mt][nf][pr2 * 2 + 0] + s_bli[c0];
                            float h2b = acc2[mt][nf][pr2 * 2 + 1] + s_bli[c0 + 1];
                            float ga  = acc3[mt][fn][pr2 * 2 + 0] + s_bd1[c0];
                            float gb  = acc3[mt][fn][pr2 * 2 + 1] + s_bd1[c0 + 1];
                            atomicAdd(&out[((size_t)pr << 6) + c0], pv * h2a * ga);
                            atomicAdd(&out[((size_t)pr << 6) + c0 + 1], pv * h2b * gb);
                        }
                    }
                }
        }
    }
}

// ============================================================================
extern "C" void kernel_launch(void* const* d_in, const int* in_sizes, int n_in,
                              void* d_out, int out_size) {
    const float* nfeat         = (const float*)d_in[0];
    const float* degs          = (const float*)d_in[1];
    const float* n2p_val       = (const float*)d_in[2];
    const float* e2p_val       = (const float*)d_in[3];
    const float* pool_val      = (const float*)d_in[4];
    const float* weights       = (const float*)d_in[5];
    const float* bias          = (const float*)d_in[6];
    const float* w_deg0        = (const float*)d_in[7];
    const float* b_deg0        = (const float*)d_in[8];
    const float* w_deg1        = (const float*)d_in[9];
    const float* b_deg1        = (const float*)d_in[10];
    const float* w_lin         = (const float*)d_in[11];
    const float* b_lin         = (const float*)d_in[12];
    const float* bond_emb      = (const float*)d_in[13];
    const int*   edge_feat_idx = (const int*)d_in[14];
    const int*   n2p_col       = (const int*)d_in[16];
    const int*   e2p_col       = (const int*)d_in[18];
    const int*   pool_row      = (const int*)d_in[19];
    float* out = (float*)d_out;

    cudaMemsetAsync(d_out, 0, (size_t)out_size * sizeof(float), 0);
    prep_kernel<<<64, 256>>>(weights, w_lin, w_deg1);

    cudaFuncSetAttribute(fused_kernel, cudaFuncAttributeMaxDynamicSharedMemorySize, SMEM_BYTES);
    fused_kernel<<<NTILES, 256, SMEM_BYTES>>>(nfeat, degs, n2p_val, e2p_val, pool_val,
                                              bias, w_deg0, b_deg0, b_deg1, b_lin,
                                              bond_emb, edge_feat_idx, n2p_col, e2p_col,
                                              pool_row, out);
}